// round 16
// baseline (speedup 1.0000x reference)
#include <cuda_runtime.h>
#include <cuda_fp16.h>

// GCN: 2x GCNConv (sym-norm, self-loops) + ReLU + final linear.
// N=100000, E=3.2M, dims 128->32->16->1.
// One-pass padded-CSR build fused with GEMM1 (roles interleaved by block
// parity). fp16 feature tables, fp32 accumulate. GEMM2 fused into agg1.
// NEW: agg gather loops use two independent chains (front+back pointers)
// to double per-thread MLP.

#define NMAX 100000
#define EMAX 3200000
#define PAD  128     // adjacency slots per node; deg ~ Binom(3.2M,1e-5), max<<128

__device__ __align__(16) int    g_pad [NMAX * PAD];  // padded adjacency (src)
__device__ __align__(16) int    g_cnt [NMAX];        // zero at entry; re-zeroed in agg2
__device__ __align__(16) float  g_dinv[NMAX];
__device__ __align__(16) __half g_h1  [NMAX * 32];   // fp16 x@W1, dinv-scaled by k_scale
__device__ __align__(16) __half g_h2  [NMAX * 16];   // fp16 dinv-prescaled a1@W2

// convert 8 fp16 (uint4) into 8 fp32 accumulators
#define ACC8(u) do { \
        const __half2* hp_ = (const __half2*)&(u); \
        float2 f0_ = __half22float2(hp_[0]); \
        float2 f1_ = __half22float2(hp_[1]); \
        float2 f2_ = __half22float2(hp_[2]); \
        float2 f3_ = __half22float2(hp_[3]); \
        a0 += f0_.x; a1 += f0_.y; a2 += f1_.x; a3 += f1_.y; \
        a4 += f2_.x; a5 += f2_.y; a6 += f3_.x; a7 += f3_.y; } while (0)

// ---------------- fused: CSR scatter + GEMM1, roles interleaved by parity
// dtype detect per-warp: int32 read as int64 has a uniform [0,1e5) high word,
// so 16 in-range int64 values is conclusive for genuine int64.
__global__ __launch_bounds__(256) void k_fused(const void* ei,
                                               const float* __restrict__ x,
                                               const float* __restrict__ W1,
                                               int E, int N, int Gs, int Gg) {
    __shared__ float Ws[128 * 32];
    __shared__ float xs[32 * 132];
    int t = threadIdx.x;
    int bid = blockIdx.x;

    // interleaved role assignment: pairs (scatter, gemm) while both remain
    int half = Gs < Gg ? Gs : Gg;
    bool is_scatter;
    int rid;
    if (bid < 2 * half) {
        is_scatter = (bid & 1) == 0;
        rid = bid >> 1;
    } else {
        is_scatter = Gs > Gg;
        rid = half + (bid - 2 * half);
    }

    if (is_scatter) {
        // ---------------- scatter role: 4 edges/thread, atomic slot claim
        const long long* p64 = (const long long*)ei;
        long long probe = p64[t & 15];
        bool bad = (probe < 0) || (probe >= N);
        bool is64 = (__ballot_sync(0xffffffffu, bad) == 0u);

        int base = 4 * (rid * 256 + t);
        if (base >= E) return;
        int s0, s1, s2, s3, d0, d1, d2, d3;
        if (is64) {
            const longlong2* ps = (const longlong2*)ei;
            const longlong2* pd = (const longlong2*)(p64 + E);
            longlong2 sa = ps[base >> 1], sb = ps[(base >> 1) + 1];
            longlong2 da = pd[base >> 1], db = pd[(base >> 1) + 1];
            s0 = (int)sa.x; s1 = (int)sa.y; s2 = (int)sb.x; s3 = (int)sb.y;
            d0 = (int)da.x; d1 = (int)da.y; d2 = (int)db.x; d3 = (int)db.y;
        } else {
            int4 sv = *(const int4*)((const int*)ei + base);
            int4 dv = *(const int4*)((const int*)ei + E + base);
            s0 = sv.x; s1 = sv.y; s2 = sv.z; s3 = sv.w;
            d0 = dv.x; d1 = dv.y; d2 = dv.z; d3 = dv.w;
        }
        if (base + 4 <= E) {
            int p0 = atomicAdd(&g_cnt[d0], 1);
            int p1 = atomicAdd(&g_cnt[d1], 1);
            int p2 = atomicAdd(&g_cnt[d2], 1);
            int p3 = atomicAdd(&g_cnt[d3], 1);
            if (p0 < PAD) g_pad[d0 * PAD + p0] = s0;
            if (p1 < PAD) g_pad[d1 * PAD + p1] = s1;
            if (p2 < PAD) g_pad[d2 * PAD + p2] = s2;
            if (p3 < PAD) g_pad[d3 * PAD + p3] = s3;
        } else {
            int ss[4] = {s0, s1, s2, s3};
            int dd[4] = {d0, d1, d2, d3};
            for (int k = 0; k < E - base; k++) {
                int p = atomicAdd(&g_cnt[dd[k]], 1);
                if (p < PAD) g_pad[dd[k] * PAD + p] = ss[k];
            }
        }
    } else {
        // ---------------- GEMM1 role: h1 = fp16(x @ W1), UNSCALED (no g_cnt)
        {
            float4* Wd = (float4*)Ws;
            const float4* Wg = (const float4*)W1;
            for (int i = t; i < 1024; i += 256) Wd[i] = Wg[i];
        }
        int base = rid * 32;
        {
            float4* xd = (float4*)xs;           // row stride 33 float4s
            const float4* xg = (const float4*)x;
            for (int i = t; i < 32 * 32; i += 256) {
                int n = i >> 5, k4 = i & 31;
                int node = base + n;
                float4 v = make_float4(0.f, 0.f, 0.f, 0.f);
                if (node < N) v = xg[(long long)node * 32 + k4];
                xd[n * 33 + k4] = v;
            }
        }
        __syncthreads();

        int f4 = t & 7;
        int n  = t >> 3;
        int node = base + n;

        float4 acc = make_float4(0.f, 0.f, 0.f, 0.f);
        const float4* Ws4 = (const float4*)Ws;
        const float4* xs4 = (const float4*)xs;
#pragma unroll
        for (int k4 = 0; k4 < 32; k4++) {
            float4 xv = xs4[n * 33 + k4];
            float4 w0 = Ws4[(k4 * 4 + 0) * 8 + f4];
            float4 w1 = Ws4[(k4 * 4 + 1) * 8 + f4];
            float4 w2 = Ws4[(k4 * 4 + 2) * 8 + f4];
            float4 w3 = Ws4[(k4 * 4 + 3) * 8 + f4];
            acc.x += xv.x * w0.x + xv.y * w1.x + xv.z * w2.x + xv.w * w3.x;
            acc.y += xv.x * w0.y + xv.y * w1.y + xv.z * w2.y + xv.w * w3.y;
            acc.z += xv.x * w0.z + xv.y * w1.z + xv.z * w2.z + xv.w * w3.z;
            acc.w += xv.x * w0.w + xv.y * w1.w + xv.z * w2.w + xv.w * w3.w;
        }
        if (node < N) {
            __half2 h0 = __floats2half2_rn(acc.x, acc.y);
            __half2 h1 = __floats2half2_rn(acc.z, acc.w);
            uint2 st;
            st.x = *(unsigned*)&h0;
            st.y = *(unsigned*)&h1;
            ((uint2*)g_h1)[(long long)node * 8 + f4] = st;
        }
    }
}

// -------- scale: dinv = rsqrt(cnt+1); h1 *= dinv (fp16 multiply)
__global__ __launch_bounds__(256) void k_scale(int N) {
    int n = blockIdx.x * blockDim.x + threadIdx.x;
    if (n >= N) return;
    float dv = rsqrtf((float)(g_cnt[n] + 1));
    g_dinv[n] = dv;
    __half2 dh = __half2half2(__float2half(dv));
    uint4* row = (uint4*)g_h1 + (long long)n * 4;
#pragma unroll
    for (int i = 0; i < 4; i++) {
        uint4 u = row[i];
        __half2* hp = (__half2*)&u;
        hp[0] = __hmul2(hp[0], dh);
        hp[1] = __hmul2(hp[1], dh);
        hp[2] = __hmul2(hp[2], dh);
        hp[3] = __hmul2(hp[3], dh);
        row[i] = u;
    }
}

// ------ agg layer1 + GEMM2 fused (smem staging):
// a1 = relu(dinv*(h1[self]+sum h1[nbr]) + b1);  h2 = fp16(dinv * (a1 @ W2))
// 256 thr = 64 nodes x 4 chunks of 8 features. Dual-ended gather chains.
__global__ __launch_bounds__(256) void k_agg1(const float* __restrict__ b1,
                                              const float* __restrict__ W2,
                                              int N) {
    __shared__ float W2s[32 * 16];           // W2[k][o] at k*16+o
    __shared__ float a1s[64 * 36];           // stride 36: conflict-free reads
    int t = threadIdx.x;
    for (int i = t; i < 512; i += 256) W2s[i] = W2[i];

    int nl = t >> 2, c = t & 3;
    int n  = blockIdx.x * 64 + nl;
    bool valid = n < N;
    int nc = valid ? n : N - 1;              // clamp for safe loads
    int cnt = g_cnt[nc];
    int end = cnt < PAD ? cnt : PAD;
    const int* row = g_pad + nc * PAD;
    const uint4* h1 = (const uint4*)g_h1;    // node row = 4 uint4 (32 fp16)

    float a0 = 0, a1 = 0, a2 = 0, a3 = 0, a4 = 0, a5 = 0, a6 = 0, a7 = 0;
    uint4 us = h1[(long long)nc * 4 + c];    // self term
    ACC8(us);
    // two independent chains: f walks from 0 up, b walks from end down
    int f = 0, b = end;
    while (b - f >= 4) {
        int sf0 = row[f], sf1 = row[f + 1];
        int sb0 = row[b - 1], sb1 = row[b - 2];
        uint4 u0 = h1[(long long)sf0 * 4 + c];
        uint4 u1 = h1[(long long)sf1 * 4 + c];
        uint4 u2 = h1[(long long)sb0 * 4 + c];
        uint4 u3 = h1[(long long)sb1 * 4 + c];
        ACC8(u0); ACC8(u1); ACC8(u2); ACC8(u3);
        f += 2; b -= 2;
    }
    while (f < b) {
        uint4 u = h1[(long long)row[f] * 4 + c];
        ACC8(u);
        f++;
    }

    float dv = g_dinv[nc];
    float4 bb0 = ((const float4*)b1)[c * 2];
    float4 bb1 = ((const float4*)b1)[c * 2 + 1];
    float4 r0, r1;
    r0.x = fmaxf(a0 * dv + bb0.x, 0.f);
    r0.y = fmaxf(a1 * dv + bb0.y, 0.f);
    r0.z = fmaxf(a2 * dv + bb0.z, 0.f);
    r0.w = fmaxf(a3 * dv + bb0.w, 0.f);
    r1.x = fmaxf(a4 * dv + bb1.x, 0.f);
    r1.y = fmaxf(a5 * dv + bb1.y, 0.f);
    r1.z = fmaxf(a6 * dv + bb1.z, 0.f);
    r1.w = fmaxf(a7 * dv + bb1.w, 0.f);
    {
        float4* dst = (float4*)(a1s + nl * 36 + c * 8);
        dst[0] = r0;
        dst[1] = r1;
    }
    __syncthreads();

    // phase 2: h2[n][c*4 .. c*4+3] = dinv * sum_k a1s[nl][k] * W2[k][c*4+j]
    float4 o = make_float4(0.f, 0.f, 0.f, 0.f);
    const float* ar = a1s + nl * 36;
#pragma unroll
    for (int k = 0; k < 32; k++) {
        float av = ar[k];
        float4 w = *(const float4*)(W2s + k * 16 + c * 4);
        o.x += av * w.x; o.y += av * w.y; o.z += av * w.z; o.w += av * w.w;
    }
    if (valid) {
        __half2 p0 = __floats2half2_rn(o.x * dv, o.y * dv);
        __half2 p1 = __floats2half2_rn(o.z * dv, o.w * dv);
        uint2 st;
        st.x = *(unsigned*)&p0;
        st.y = *(unsigned*)&p1;
        ((uint2*)g_h2)[(long long)n * 4 + c] = st;   // row = 4 uint2 (16 fp16)
    }
}

// ------ agg layer2 + final: out = relu(dinv*sum + b2) @ Wf + bf
// 2 threads/node, 8 fp16 features (uint4) each. Dual-ended gather chains.
// Also re-zeroes g_cnt for the next replay.
__global__ __launch_bounds__(256) void k_agg2(const float* __restrict__ b2,
                                              const float* __restrict__ Wf,
                                              const float* __restrict__ bf,
                                              float* __restrict__ out, int N) {
    int idx = blockIdx.x * blockDim.x + threadIdx.x;
    int n = idx >> 1, c = idx & 1;
    bool valid = n < N;
    if (!valid) n = N - 1;
    int cnt = g_cnt[n];
    int end = cnt < PAD ? cnt : PAD;
    const int* row = g_pad + n * PAD;
    const uint4* h2 = (const uint4*)g_h2;    // node row = 2 uint4 (16 fp16)

    float a0 = 0, a1 = 0, a2 = 0, a3 = 0, a4 = 0, a5 = 0, a6 = 0, a7 = 0;
    uint4 us = h2[(long long)n * 2 + c];     // self term
    ACC8(us);
    int f = 0, b = end;
    while (b - f >= 4) {
        int sf0 = row[f], sf1 = row[f + 1];
        int sb0 = row[b - 1], sb1 = row[b - 2];
        uint4 u0 = h2[(long long)sf0 * 2 + c];
        uint4 u1 = h2[(long long)sf1 * 2 + c];
        uint4 u2 = h2[(long long)sb0 * 2 + c];
        uint4 u3 = h2[(long long)sb1 * 2 + c];
        ACC8(u0); ACC8(u1); ACC8(u2); ACC8(u3);
        f += 2; b -= 2;
    }
    while (f < b) {
        uint4 u = h2[(long long)row[f] * 2 + c];
        ACC8(u);
        f++;
    }
    float dv = g_dinv[n];
    float4 bb0 = ((const float4*)b2)[c * 2];
    float4 bb1 = ((const float4*)b2)[c * 2 + 1];
    float4 w0  = ((const float4*)Wf)[c * 2];
    float4 w1  = ((const float4*)Wf)[c * 2 + 1];
    float p = fmaxf(a0 * dv + bb0.x, 0.f) * w0.x
            + fmaxf(a1 * dv + bb0.y, 0.f) * w0.y
            + fmaxf(a2 * dv + bb0.z, 0.f) * w0.z
            + fmaxf(a3 * dv + bb0.w, 0.f) * w0.w
            + fmaxf(a4 * dv + bb1.x, 0.f) * w1.x
            + fmaxf(a5 * dv + bb1.y, 0.f) * w1.y
            + fmaxf(a6 * dv + bb1.z, 0.f) * w1.z
            + fmaxf(a7 * dv + bb1.w, 0.f) * w1.w;
    p += __shfl_xor_sync(0xffffffffu, p, 1);
    if (valid && c == 0) {
        out[n] = p + __ldg(&bf[0]);
        g_cnt[n] = 0;                        // restore invariant for next replay
    }
}

// ---------------------------------------------------------------- launcher
extern "C" void kernel_launch(void* const* d_in, const int* in_sizes, int n_in,
                              void* d_out, int out_size) {
    const float* x  = (const float*)d_in[0];
    const void*  ei = d_in[1];
    const float* W1 = (const float*)d_in[2];
    const float* b1 = (const float*)d_in[3];
    const float* W2 = (const float*)d_in[4];
    const float* b2 = (const float*)d_in[5];
    const float* Wf = (const float*)d_in[6];
    const float* bf = (const float*)d_in[7];
    float* out = (float*)d_out;

    int N = in_sizes[0] / 128;   // 100000
    int E = in_sizes[1] / 2;     // 3200000
    int Eq = (E + 3) / 4;
    int Gs = (Eq + 255) / 256;   // scatter blocks (3125)
    int Gg = (N + 31) / 32;      // gemm1 blocks   (3125)

    k_fused<<<Gs + Gg, 256>>>(ei, x, W1, E, N, Gs, Gg);
    k_scale<<<(N + 255) / 256, 256>>>(N);
    k_agg1 <<<(N + 63) / 64, 256>>>(b1, W2, N);
    k_agg2 <<<(N * 2 + 255) / 256, 256>>>(b2, Wf, bf, out, N);
}

// round 17
// speedup vs baseline: 1.0307x; 1.0307x over previous
#include <cuda_runtime.h>
#include <cuda_fp16.h>

// GCN: 2x GCNConv (sym-norm, self-loops) + ReLU + final linear.
// N=100000, E=3.2M, dims 128->32->16->1.
// One-pass padded-CSR build fused with GEMM1 (roles interleaved by block
// parity). fp16 feature tables, fp32 accumulate. GEMM2 fused into agg1.
// Agg gathers: two int4-aligned index chains walked in lockstep
// (8 independent feature loads + 2 index loads in flight per iteration).

#define NMAX 100000
#define EMAX 3200000
#define PAD  128     // adjacency slots per node; deg ~ Binom(3.2M,1e-5), max<<128

__device__ __align__(16) int    g_pad [NMAX * PAD];  // padded adjacency (src)
__device__ __align__(16) int    g_cnt [NMAX];        // zero at entry; re-zeroed in agg2
__device__ __align__(16) float  g_dinv[NMAX];
__device__ __align__(16) __half g_h1  [NMAX * 32];   // fp16 x@W1, dinv-scaled by k_scale
__device__ __align__(16) __half g_h2  [NMAX * 16];   // fp16 dinv-prescaled a1@W2

// convert 8 fp16 (uint4) into 8 fp32 accumulators
#define ACC8(u) do { \
        const __half2* hp_ = (const __half2*)&(u); \
        float2 f0_ = __half22float2(hp_[0]); \
        float2 f1_ = __half22float2(hp_[1]); \
        float2 f2_ = __half22float2(hp_[2]); \
        float2 f3_ = __half22float2(hp_[3]); \
        a0 += f0_.x; a1 += f0_.y; a2 += f1_.x; a3 += f1_.y; \
        a4 += f2_.x; a5 += f2_.y; a6 += f3_.x; a7 += f3_.y; } while (0)

// ---------------- fused: CSR scatter + GEMM1, roles interleaved by parity
// dtype detect per-warp: int32 read as int64 has a uniform [0,1e5) high word,
// so 16 in-range int64 values is conclusive for genuine int64.
__global__ __launch_bounds__(256) void k_fused(const void* ei,
                                               const float* __restrict__ x,
                                               const float* __restrict__ W1,
                                               int E, int N, int Gs, int Gg) {
    __shared__ float Ws[128 * 32];
    __shared__ float xs[32 * 132];
    int t = threadIdx.x;
    int bid = blockIdx.x;

    int half = Gs < Gg ? Gs : Gg;
    bool is_scatter;
    int rid;
    if (bid < 2 * half) {
        is_scatter = (bid & 1) == 0;
        rid = bid >> 1;
    } else {
        is_scatter = Gs > Gg;
        rid = half + (bid - 2 * half);
    }

    if (is_scatter) {
        // ---------------- scatter role: 4 edges/thread, atomic slot claim
        const long long* p64 = (const long long*)ei;
        long long probe = p64[t & 15];
        bool bad = (probe < 0) || (probe >= N);
        bool is64 = (__ballot_sync(0xffffffffu, bad) == 0u);

        int base = 4 * (rid * 256 + t);
        if (base >= E) return;
        int s0, s1, s2, s3, d0, d1, d2, d3;
        if (is64) {
            const longlong2* ps = (const longlong2*)ei;
            const longlong2* pd = (const longlong2*)(p64 + E);
            longlong2 sa = ps[base >> 1], sb = ps[(base >> 1) + 1];
            longlong2 da = pd[base >> 1], db = pd[(base >> 1) + 1];
            s0 = (int)sa.x; s1 = (int)sa.y; s2 = (int)sb.x; s3 = (int)sb.y;
            d0 = (int)da.x; d1 = (int)da.y; d2 = (int)db.x; d3 = (int)db.y;
        } else {
            int4 sv = *(const int4*)((const int*)ei + base);
            int4 dv = *(const int4*)((const int*)ei + E + base);
            s0 = sv.x; s1 = sv.y; s2 = sv.z; s3 = sv.w;
            d0 = dv.x; d1 = dv.y; d2 = dv.z; d3 = dv.w;
        }
        if (base + 4 <= E) {
            int p0 = atomicAdd(&g_cnt[d0], 1);
            int p1 = atomicAdd(&g_cnt[d1], 1);
            int p2 = atomicAdd(&g_cnt[d2], 1);
            int p3 = atomicAdd(&g_cnt[d3], 1);
            if (p0 < PAD) g_pad[d0 * PAD + p0] = s0;
            if (p1 < PAD) g_pad[d1 * PAD + p1] = s1;
            if (p2 < PAD) g_pad[d2 * PAD + p2] = s2;
            if (p3 < PAD) g_pad[d3 * PAD + p3] = s3;
        } else {
            int ss[4] = {s0, s1, s2, s3};
            int dd[4] = {d0, d1, d2, d3};
            for (int k = 0; k < E - base; k++) {
                int p = atomicAdd(&g_cnt[dd[k]], 1);
                if (p < PAD) g_pad[dd[k] * PAD + p] = ss[k];
            }
        }
    } else {
        // ---------------- GEMM1 role: h1 = fp16(x @ W1), UNSCALED (no g_cnt)
        {
            float4* Wd = (float4*)Ws;
            const float4* Wg = (const float4*)W1;
            for (int i = t; i < 1024; i += 256) Wd[i] = Wg[i];
        }
        int base = rid * 32;
        {
            float4* xd = (float4*)xs;           // row stride 33 float4s
            const float4* xg = (const float4*)x;
            for (int i = t; i < 32 * 32; i += 256) {
                int n = i >> 5, k4 = i & 31;
                int node = base + n;
                float4 v = make_float4(0.f, 0.f, 0.f, 0.f);
                if (node < N) v = xg[(long long)node * 32 + k4];
                xd[n * 33 + k4] = v;
            }
        }
        __syncthreads();

        int f4 = t & 7;
        int n  = t >> 3;
        int node = base + n;

        float4 acc = make_float4(0.f, 0.f, 0.f, 0.f);
        const float4* Ws4 = (const float4*)Ws;
        const float4* xs4 = (const float4*)xs;
#pragma unroll
        for (int k4 = 0; k4 < 32; k4++) {
            float4 xv = xs4[n * 33 + k4];
            float4 w0 = Ws4[(k4 * 4 + 0) * 8 + f4];
            float4 w1 = Ws4[(k4 * 4 + 1) * 8 + f4];
            float4 w2 = Ws4[(k4 * 4 + 2) * 8 + f4];
            float4 w3 = Ws4[(k4 * 4 + 3) * 8 + f4];
            acc.x += xv.x * w0.x + xv.y * w1.x + xv.z * w2.x + xv.w * w3.x;
            acc.y += xv.x * w0.y + xv.y * w1.y + xv.z * w2.y + xv.w * w3.y;
            acc.z += xv.x * w0.z + xv.y * w1.z + xv.z * w2.z + xv.w * w3.z;
            acc.w += xv.x * w0.w + xv.y * w1.w + xv.z * w2.w + xv.w * w3.w;
        }
        if (node < N) {
            __half2 h0 = __floats2half2_rn(acc.x, acc.y);
            __half2 h1 = __floats2half2_rn(acc.z, acc.w);
            uint2 st;
            st.x = *(unsigned*)&h0;
            st.y = *(unsigned*)&h1;
            ((uint2*)g_h1)[(long long)node * 8 + f4] = st;
        }
    }
}

// -------- scale: dinv = rsqrt(cnt+1); h1 *= dinv (fp16 multiply)
__global__ __launch_bounds__(256) void k_scale(int N) {
    int n = blockIdx.x * blockDim.x + threadIdx.x;
    if (n >= N) return;
    float dv = rsqrtf((float)(g_cnt[n] + 1));
    g_dinv[n] = dv;
    __half2 dh = __half2half2(__float2half(dv));
    uint4* row = (uint4*)g_h1 + (long long)n * 4;
#pragma unroll
    for (int i = 0; i < 4; i++) {
        uint4 u = row[i];
        __half2* hp = (__half2*)&u;
        hp[0] = __hmul2(hp[0], dh);
        hp[1] = __hmul2(hp[1], dh);
        hp[2] = __hmul2(hp[2], dh);
        hp[3] = __hmul2(hp[3], dh);
        row[i] = u;
    }
}

// ------ agg layer1 + GEMM2 fused (smem staging):
// a1 = relu(dinv*(h1[self]+sum h1[nbr]) + b1);  h2 = fp16(dinv * (a1 @ W2))
// 256 thr = 64 nodes x 4 chunks of 8 features. Dual int4 index chains.
__global__ __launch_bounds__(256) void k_agg1(const float* __restrict__ b1,
                                              const float* __restrict__ W2,
                                              int N) {
    __shared__ float W2s[32 * 16];           // W2[k][o] at k*16+o
    __shared__ float a1s[64 * 36];           // stride 36: conflict-free reads
    int t = threadIdx.x;
    for (int i = t; i < 512; i += 256) W2s[i] = W2[i];

    int nl = t >> 2, c = t & 3;
    int n  = blockIdx.x * 64 + nl;
    bool valid = n < N;
    int nc = valid ? n : N - 1;              // clamp for safe loads
    int cnt = g_cnt[nc];
    int end = cnt < PAD ? cnt : PAD;
    const int4* r4 = (const int4*)(g_pad + nc * PAD);     // 16B-aligned row
    const uint4* h1 = (const uint4*)g_h1;    // node row = 4 uint4 (32 fp16)

    float a0 = 0, a1 = 0, a2 = 0, a3 = 0, a4 = 0, a5 = 0, a6 = 0, a7 = 0;
    uint4 us = h1[(long long)nc * 4 + c];    // self term
    ACC8(us);

    int mid = (end >> 1) & ~3;               // chain split, multiple of 4
    int j1 = 0, j2 = mid;
    // lockstep dual chains: 2 int4 index loads + 8 feature loads in flight
    while (j1 + 4 <= mid && j2 + 4 <= end) {
        int4 sa = r4[j1 >> 2];
        int4 sb = r4[j2 >> 2];
        uint4 u0 = h1[(long long)sa.x * 4 + c];
        uint4 u1 = h1[(long long)sa.y * 4 + c];
        uint4 u2 = h1[(long long)sa.z * 4 + c];
        uint4 u3 = h1[(long long)sa.w * 4 + c];
        uint4 u4 = h1[(long long)sb.x * 4 + c];
        uint4 u5 = h1[(long long)sb.y * 4 + c];
        uint4 u6 = h1[(long long)sb.z * 4 + c];
        uint4 u7 = h1[(long long)sb.w * 4 + c];
        ACC8(u0); ACC8(u1); ACC8(u2); ACC8(u3);
        ACC8(u4); ACC8(u5); ACC8(u6); ACC8(u7);
        j1 += 4; j2 += 4;
    }
    while (j2 + 4 <= end) {                   // chain-2 full groups
        int4 sb = r4[j2 >> 2];
        uint4 u0 = h1[(long long)sb.x * 4 + c];
        uint4 u1 = h1[(long long)sb.y * 4 + c];
        uint4 u2 = h1[(long long)sb.z * 4 + c];
        uint4 u3 = h1[(long long)sb.w * 4 + c];
        ACC8(u0); ACC8(u1); ACC8(u2); ACC8(u3);
        j2 += 4;
    }
    if (j2 < end) {                           // chain-2 tail (<4), padded-safe
        int4 sb = r4[j2 >> 2];
        int rem = end - j2;
        uint4 u = h1[(long long)sb.x * 4 + c];
        ACC8(u);
        if (rem > 1) { uint4 u1 = h1[(long long)sb.y * 4 + c]; ACC8(u1); }
        if (rem > 2) { uint4 u2 = h1[(long long)sb.z * 4 + c]; ACC8(u2); }
    }
    // chain-1 has no tail: mid is a multiple of 4

    float dv = g_dinv[nc];
    float4 bb0 = ((const float4*)b1)[c * 2];
    float4 bb1 = ((const float4*)b1)[c * 2 + 1];
    float4 r0, r1;
    r0.x = fmaxf(a0 * dv + bb0.x, 0.f);
    r0.y = fmaxf(a1 * dv + bb0.y, 0.f);
    r0.z = fmaxf(a2 * dv + bb0.z, 0.f);
    r0.w = fmaxf(a3 * dv + bb0.w, 0.f);
    r1.x = fmaxf(a4 * dv + bb1.x, 0.f);
    r1.y = fmaxf(a5 * dv + bb1.y, 0.f);
    r1.z = fmaxf(a6 * dv + bb1.z, 0.f);
    r1.w = fmaxf(a7 * dv + bb1.w, 0.f);
    {
        float4* dst = (float4*)(a1s + nl * 36 + c * 8);
        dst[0] = r0;
        dst[1] = r1;
    }
    __syncthreads();

    // phase 2: h2[n][c*4 .. c*4+3] = dinv * sum_k a1s[nl][k] * W2[k][c*4+j]
    float4 o = make_float4(0.f, 0.f, 0.f, 0.f);
    const float* ar = a1s + nl * 36;
#pragma unroll
    for (int k = 0; k < 32; k++) {
        float av = ar[k];
        float4 w = *(const float4*)(W2s + k * 16 + c * 4);
        o.x += av * w.x; o.y += av * w.y; o.z += av * w.z; o.w += av * w.w;
    }
    if (valid) {
        __half2 p0 = __floats2half2_rn(o.x * dv, o.y * dv);
        __half2 p1 = __floats2half2_rn(o.z * dv, o.w * dv);
        uint2 st;
        st.x = *(unsigned*)&p0;
        st.y = *(unsigned*)&p1;
        ((uint2*)g_h2)[(long long)n * 4 + c] = st;   // row = 4 uint2 (16 fp16)
    }
}

// ------ agg layer2 + final: out = relu(dinv*sum + b2) @ Wf + bf
// 2 threads/node, 8 fp16 features (uint4) each. Dual int4 index chains.
// Also re-zeroes g_cnt for the next replay.
__global__ __launch_bounds__(256) void k_agg2(const float* __restrict__ b2,
                                              const float* __restrict__ Wf,
                                              const float* __restrict__ bf,
                                              float* __restrict__ out, int N) {
    int idx = blockIdx.x * blockDim.x + threadIdx.x;
    int n = idx >> 1, c = idx & 1;
    bool valid = n < N;
    if (!valid) n = N - 1;
    int cnt = g_cnt[n];
    int end = cnt < PAD ? cnt : PAD;
    const int4* r4 = (const int4*)(g_pad + n * PAD);
    const uint4* h2 = (const uint4*)g_h2;    // node row = 2 uint4 (16 fp16)

    float a0 = 0, a1 = 0, a2 = 0, a3 = 0, a4 = 0, a5 = 0, a6 = 0, a7 = 0;
    uint4 us = h2[(long long)n * 2 + c];     // self term
    ACC8(us);

    int mid = (end >> 1) & ~3;
    int j1 = 0, j2 = mid;
    while (j1 + 4 <= mid && j2 + 4 <= end) {
        int4 sa = r4[j1 >> 2];
        int4 sb = r4[j2 >> 2];
        uint4 u0 = h2[(long long)sa.x * 2 + c];
        uint4 u1 = h2[(long long)sa.y * 2 + c];
        uint4 u2 = h2[(long long)sa.z * 2 + c];
        uint4 u3 = h2[(long long)sa.w * 2 + c];
        uint4 u4 = h2[(long long)sb.x * 2 + c];
        uint4 u5 = h2[(long long)sb.y * 2 + c];
        uint4 u6 = h2[(long long)sb.z * 2 + c];
        uint4 u7 = h2[(long long)sb.w * 2 + c];
        ACC8(u0); ACC8(u1); ACC8(u2); ACC8(u3);
        ACC8(u4); ACC8(u5); ACC8(u6); ACC8(u7);
        j1 += 4; j2 += 4;
    }
    while (j2 + 4 <= end) {
        int4 sb = r4[j2 >> 2];
        uint4 u0 = h2[(long long)sb.x * 2 + c];
        uint4 u1 = h2[(long long)sb.y * 2 + c];
        uint4 u2 = h2[(long long)sb.z * 2 + c];
        uint4 u3 = h2[(long long)sb.w * 2 + c];
        ACC8(u0); ACC8(u1); ACC8(u2); ACC8(u3);
        j2 += 4;
    }
    if (j2 < end) {
        int4 sb = r4[j2 >> 2];
        int rem = end - j2;
        uint4 u = h2[(long long)sb.x * 2 + c];
        ACC8(u);
        if (rem > 1) { uint4 u1 = h2[(long long)sb.y * 2 + c]; ACC8(u1); }
        if (rem > 2) { uint4 u2 = h2[(long long)sb.z * 2 + c]; ACC8(u2); }
    }

    float dv = g_dinv[n];
    float4 bb0 = ((const float4*)b2)[c * 2];
    float4 bb1 = ((const float4*)b2)[c * 2 + 1];
    float4 w0  = ((const float4*)Wf)[c * 2];
    float4 w1  = ((const float4*)Wf)[c * 2 + 1];
    float p = fmaxf(a0 * dv + bb0.x, 0.f) * w0.x
            + fmaxf(a1 * dv + bb0.y, 0.f) * w0.y
            + fmaxf(a2 * dv + bb0.z, 0.f) * w0.z
            + fmaxf(a3 * dv + bb0.w, 0.f) * w0.w
            + fmaxf(a4 * dv + bb1.x, 0.f) * w1.x
            + fmaxf(a5 * dv + bb1.y, 0.f) * w1.y
            + fmaxf(a6 * dv + bb1.z, 0.f) * w1.z
            + fmaxf(a7 * dv + bb1.w, 0.f) * w1.w;
    p += __shfl_xor_sync(0xffffffffu, p, 1);
    if (valid && c == 0) {
        out[n] = p + __ldg(&bf[0]);
        g_cnt[n] = 0;                        // restore invariant for next replay
    }
}

// ---------------------------------------------------------------- launcher
extern "C" void kernel_launch(void* const* d_in, const int* in_sizes, int n_in,
                              void* d_out, int out_size) {
    const float* x  = (const float*)d_in[0];
    const void*  ei = d_in[1];
    const float* W1 = (const float*)d_in[2];
    const float* b1 = (const float*)d_in[3];
    const float* W2 = (const float*)d_in[4];
    const float* b2 = (const float*)d_in[5];
    const float* Wf = (const float*)d_in[6];
    const float* bf = (const float*)d_in[7];
    float* out = (float*)d_out;

    int N = in_sizes[0] / 128;   // 100000
    int E = in_sizes[1] / 2;     // 3200000
    int Eq = (E + 3) / 4;
    int Gs = (Eq + 255) / 256;   // scatter blocks (3125)
    int Gg = (N + 31) / 32;      // gemm1 blocks   (3125)

    k_fused<<<Gs + Gg, 256>>>(ei, x, W1, E, N, Gs, Gg);
    k_scale<<<(N + 255) / 256, 256>>>(N);
    k_agg1 <<<(N + 63) / 64, 256>>>(b1, W2, N);
    k_agg2 <<<(N * 2 + 255) / 256, 256>>>(b2, Wf, bf, out, N);
}